// round 3
// baseline (speedup 1.0000x reference)
#include <cuda_runtime.h>
#include <cstdint>
#include <cstddef>

#define B_   2048
#define T_   512
#define I_   58
#define H_   23
#define G_   69      // 3*H
#define GP_  72      // padded gate dim (8 col-threads * 9 cols)
#define ROWS_TOTAL (B_ * T_)          // 1048576
#define RPB  128                      // rows per block (xproj)
#define XS_STRIDE (RPB + 2)           // pad 2: conflict-light writes + 8B-aligned rows

// 290 MB scratch for x_proj, layout [b][t][g] == [row][g]
__device__ float g_xp[(size_t)ROWS_TOTAL * G_];

// ---------- packed f32x2 helpers (Blackwell FFMA2) ----------
__device__ __forceinline__ unsigned long long fma2_(unsigned long long a,
                                                    unsigned long long b,
                                                    unsigned long long c) {
    unsigned long long d;
    asm("fma.rn.f32x2 %0, %1, %2, %3;" : "=l"(d) : "l"(a), "l"(b), "l"(c));
    return d;
}
__device__ __forceinline__ unsigned long long pack2_(float lo, float hi) {
    unsigned long long d;
    asm("mov.b64 %0, {%1, %2};"
        : "=l"(d) : "r"(__float_as_uint(lo)), "r"(__float_as_uint(hi)));
    return d;
}
__device__ __forceinline__ void unpack2_(unsigned long long v, float& lo, float& hi) {
    unsigned int ulo, uhi;
    asm("mov.b64 {%0, %1}, %2;" : "=r"(ulo), "=r"(uhi) : "l"(v));
    lo = __uint_as_float(ulo);
    hi = __uint_as_float(uhi);
}

// ---------- fast gate functions (MUFU-based, ~1e-6 rel err) ----------
__device__ __forceinline__ float sigmoidf_(float x) {
    return __fdividef(1.f, 1.f + __expf(-x));
}
__device__ __forceinline__ float tanhf_(float x) {
    return 1.f - __fdividef(2.f, __expf(2.f * x) + 1.f);
}

// =====================================================================
// Kernel 1: x_proj[row][g] = task_seq[row] . W_ih[g] + b_ih[g]
// Block tile: 128 rows x 72 cols. 128 threads.
// Thread tile: 8 rows (4 f32x2 pairs) x 9 cols. FFMA2-bound inner loop.
// =====================================================================
__global__ void __launch_bounds__(128) xproj_kernel(
    const float* __restrict__ ts,
    const float* __restrict__ Wih,
    const float* __restrict__ bih)
{
    __shared__ __align__(16) float xs[I_][XS_STRIDE];
    __shared__ float ws[I_][GP_];

    const int tid = threadIdx.x;
    const size_t row0 = (size_t)blockIdx.x * RPB;

    // Load W_ih (transposed into [k][g]), zero-pad g in [69,72)
    for (int idx = tid; idx < I_ * GP_; idx += 128) {
        int k = idx / GP_, g = idx - k * GP_;
        ws[k][g] = (g < G_) ? Wih[g * I_ + k] : 0.f;
    }
    // Load 128 input rows, transposed into [k][r] (global reads coalesced)
    for (int idx = tid; idx < RPB * I_; idx += 128) {
        int r = idx / I_, k = idx - r * I_;
        xs[k][r] = ts[(row0 + r) * I_ + k];
    }
    __syncthreads();

    const int tx = tid & 7;         // col group 0..7
    const int ty = tid >> 3;        // row group 0..15
    const int rbase = ty * 8;
    const int gbase = tx * 9;

    unsigned long long acc[4][9];
    #pragma unroll
    for (int rp = 0; rp < 4; rp++)
        #pragma unroll
        for (int c = 0; c < 9; c++)
            acc[rp][c] = 0ull;

    #pragma unroll 2
    for (int k = 0; k < I_; k++) {
        unsigned long long xv[4];
        #pragma unroll
        for (int rp = 0; rp < 4; rp++)
            xv[rp] = *reinterpret_cast<const unsigned long long*>(&xs[k][rbase + 2 * rp]);
        #pragma unroll
        for (int c = 0; c < 9; c++) {
            float w = ws[k][gbase + c];
            unsigned long long w2 = pack2_(w, w);
            #pragma unroll
            for (int rp = 0; rp < 4; rp++)
                acc[rp][c] = fma2_(xv[rp], w2, acc[rp][c]);
        }
    }

    // Epilogue: add b_ih, write to g_xp (streaming, row-major)
    float bv[9];
    #pragma unroll
    for (int c = 0; c < 9; c++) {
        int g = gbase + c;
        bv[c] = (g < G_) ? __ldg(&bih[g]) : 0.f;
    }
    #pragma unroll
    for (int rp = 0; rp < 4; rp++) {
        size_t r0 = row0 + rbase + 2 * rp;
        #pragma unroll
        for (int c = 0; c < 9; c++) {
            int g = gbase + c;
            if (g < G_) {
                float lo, hi;
                unpack2_(acc[rp][c], lo, hi);
                g_xp[r0 * G_ + g]       = lo + bv[c];
                g_xp[(r0 + 1) * G_ + g] = hi + bv[c];
            }
        }
    }
}

// =====================================================================
// Kernel 2: GRU scan. Thread = (batch, j). 69 W_hh weights in registers,
// h state in double-buffered shared (1 barrier/step), x prefetched 1 step
// ahead. 14 batches/block -> 147 blocks ~ one per SM.
// =====================================================================
#define BPB 14
#define SCAN_THREADS 352   // 11 full warps; 322 active

__global__ void __launch_bounds__(SCAN_THREADS) gru_scan_kernel(
    const float* __restrict__ Whh,
    const float* __restrict__ bhh,
    const float* __restrict__ piw,
    const float* __restrict__ pib,
    float* __restrict__ out)
{
    __shared__ float hbuf[2][BPB][24];  // pad 24

    const int tid = threadIdx.x;
    const int bl  = tid / H_;
    const int j   = tid - bl * H_;
    const int bg  = blockIdx.x * BPB + bl;
    const bool active = (tid < BPB * H_) && (bg < B_);

    float Wr[H_], Wz[H_], Wn[H_];
    float br = 0.f, bz = 0.f, bn = 0.f, pw = 0.f, pb = 0.f;
    if (active) {
        #pragma unroll
        for (int k = 0; k < H_; k++) {
            Wr[k] = Whh[j * H_ + k];
            Wz[k] = Whh[(H_ + j) * H_ + k];
            Wn[k] = Whh[(2 * H_ + j) * H_ + k];
        }
        br = bhh[j]; bz = bhh[H_ + j]; bn = bhh[2 * H_ + j];
        pw = piw[j]; pb = pib[j];
        hbuf[0][bl][j] = 0.f;
    }
    __syncthreads();

    const int bsafe = active ? bg : 0;
    const float* xptr = g_xp + (size_t)bsafe * T_ * G_;
    float*       optr = out  + (size_t)bsafe * T_ * H_ + j;

    float h = 0.f;
    float xr = 0.f, xz = 0.f, xn = 0.f;
    if (active) { xr = xptr[j]; xz = xptr[H_ + j]; xn = xptr[2 * H_ + j]; }

    int p = 0;
    for (int t = 0; t < T_; t++) {
        // Prefetch next step's x (independent of recurrence -> full step to land)
        float nr = 0.f, nz = 0.f, nn = 0.f;
        if (active && (t + 1 < T_)) {
            const float* q = xptr + G_;
            nr = q[j]; nz = q[H_ + j]; nn = q[2 * H_ + j];
        }
        if (active) {
            float ar = br, az = bz, an = bn;
            const float* hb = hbuf[p][bl];
            #pragma unroll
            for (int k = 0; k < H_; k++) {
                float hk = hb[k];
                ar = fmaf(Wr[k], hk, ar);
                az = fmaf(Wz[k], hk, az);
                an = fmaf(Wn[k], hk, an);
            }
            float r = sigmoidf_(xr + ar);
            float z = sigmoidf_(xz + az);
            float n = tanhf_(xn + r * an);
            h = fmaf(z, h - n, n);          // (1-z)*n + z*h
            hbuf[p ^ 1][bl][j] = h;
            *optr = fmaf(pw, h, pb);        // action_pred
        }
        __syncthreads();
        p ^= 1;
        xr = nr; xz = nz; xn = nn;
        xptr += G_;
        optr += H_;
    }

    if (active) {
        // hidden = hT, appended after action_pred
        out[(size_t)B_ * T_ * H_ + (size_t)bg * H_ + j] = h;
    }
}

// =====================================================================
extern "C" void kernel_launch(void* const* d_in, const int* in_sizes, int n_in,
                              void* d_out, int out_size)
{
    const float* ts  = (const float*)d_in[0];  // task_seq (B,T,I)
    const float* Wih = (const float*)d_in[1];  // (69,58)
    const float* Whh = (const float*)d_in[2];  // (69,23)
    const float* bih = (const float*)d_in[3];  // (69,)
    const float* bhh = (const float*)d_in[4];  // (69,)
    const float* piw = (const float*)d_in[5];  // (23,)
    const float* pib = (const float*)d_in[6];  // (23,)
    float* out = (float*)d_out;

    xproj_kernel<<<ROWS_TOTAL / RPB, 128>>>(ts, Wih, bih);
    gru_scan_kernel<<<(B_ + BPB - 1) / BPB, SCAN_THREADS>>>(Whh, bhh, piw, pib, out);
}

// round 4
// speedup vs baseline: 1.4934x; 1.4934x over previous
#include <cuda_runtime.h>
#include <cstdint>
#include <cstddef>

#define B_   2048
#define T_   512
#define I_   58
#define H_   23
#define G_   69      // 3*H
#define GP_  72      // padded gate dim (8 col-threads * 9 cols)
#define ROWS_TOTAL (B_ * T_)          // 1048576
#define RPB  128                      // rows per block (xproj)
#define XS_STRIDE (RPB + 2)

// 290 MB scratch for x_proj, layout [b][t][g] == [row][g]
__device__ float g_xp[(size_t)ROWS_TOTAL * G_];

// ---------- packed f32x2 helpers (Blackwell FFMA2) ----------
__device__ __forceinline__ unsigned long long fma2_(unsigned long long a,
                                                    unsigned long long b,
                                                    unsigned long long c) {
    unsigned long long d;
    asm("fma.rn.f32x2 %0, %1, %2, %3;" : "=l"(d) : "l"(a), "l"(b), "l"(c));
    return d;
}
__device__ __forceinline__ unsigned long long pack2_(float lo, float hi) {
    unsigned long long d;
    asm("mov.b64 %0, {%1, %2};"
        : "=l"(d) : "r"(__float_as_uint(lo)), "r"(__float_as_uint(hi)));
    return d;
}
__device__ __forceinline__ void unpack2_(unsigned long long v, float& lo, float& hi) {
    unsigned int ulo, uhi;
    asm("mov.b64 {%0, %1}, %2;" : "=r"(ulo), "=r"(uhi) : "l"(v));
    lo = __uint_as_float(ulo);
    hi = __uint_as_float(uhi);
}

// ---------- fast gate functions (MUFU-based, ~1e-6 rel err) ----------
__device__ __forceinline__ float sigmoidf_(float x) {
    return __fdividef(1.f, 1.f + __expf(-x));
}
__device__ __forceinline__ float tanhf_(float x) {
    return 1.f - __fdividef(2.f, __expf(2.f * x) + 1.f);
}

// =====================================================================
// Kernel 1: x_proj[row][g] = task_seq[row] . W_ih[g] + b_ih[g]
// 128 rows x 72 cols per block, 128 threads, 8x9 thread tile, FFMA2.
// Output staged in shared (union over input tiles) then flushed with
// fully coalesced STG.128 (kills the 8x store amplification of R3).
// =====================================================================
struct __align__(16) SmemU {
    union {
        struct {
            float xs[I_][XS_STRIDE];   // 30160 B
            float ws[I_][GP_];         // 16704 B  -> 46864 B
        } a;
        float os[RPB * G_];            // 35328 B
    };
};

__global__ void __launch_bounds__(128) xproj_kernel(
    const float* __restrict__ ts,
    const float* __restrict__ Wih,
    const float* __restrict__ bih)
{
    __shared__ SmemU u;

    const int tid = threadIdx.x;
    const size_t row0 = (size_t)blockIdx.x * RPB;

    // Load W_ih (transposed into [k][g]), zero-pad g in [69,72)
    for (int idx = tid; idx < I_ * GP_; idx += 128) {
        int k = idx / GP_, g = idx - k * GP_;
        u.a.ws[k][g] = (g < G_) ? Wih[g * I_ + k] : 0.f;
    }
    // Load 128 input rows, transposed into [k][r]
    for (int idx = tid; idx < RPB * I_; idx += 128) {
        int r = idx / I_, k = idx - r * I_;
        u.a.xs[k][r] = ts[(row0 + r) * I_ + k];
    }
    __syncthreads();

    const int tx = tid & 7;         // col group 0..7
    const int ty = tid >> 3;        // row group 0..15
    const int rbase = ty * 8;
    const int gbase = tx * 9;

    unsigned long long acc[4][9];
    #pragma unroll
    for (int rp = 0; rp < 4; rp++)
        #pragma unroll
        for (int c = 0; c < 9; c++)
            acc[rp][c] = 0ull;

    #pragma unroll 2
    for (int k = 0; k < I_; k++) {
        unsigned long long xv[4];
        #pragma unroll
        for (int rp = 0; rp < 4; rp++)
            xv[rp] = *reinterpret_cast<const unsigned long long*>(&u.a.xs[k][rbase + 2 * rp]);
        #pragma unroll
        for (int c = 0; c < 9; c++) {
            float w = u.a.ws[k][gbase + c];
            unsigned long long w2 = pack2_(w, w);
            #pragma unroll
            for (int rp = 0; rp < 4; rp++)
                acc[rp][c] = fma2_(xv[rp], w2, acc[rp][c]);
        }
    }

    float bv[9];
    #pragma unroll
    for (int c = 0; c < 9; c++) {
        int g = gbase + c;
        bv[c] = (g < G_) ? __ldg(&bih[g]) : 0.f;
    }

    __syncthreads();   // inputs fully consumed -> safe to overwrite union

    // Stage results in shared, layout identical to global [r][g]
    #pragma unroll
    for (int rp = 0; rp < 4; rp++) {
        int r0 = rbase + 2 * rp;
        #pragma unroll
        for (int c = 0; c < 9; c++) {
            int g = gbase + c;
            if (g < G_) {
                float lo, hi;
                unpack2_(acc[rp][c], lo, hi);
                u.os[r0 * G_ + g]       = lo + bv[c];
                u.os[(r0 + 1) * G_ + g] = hi + bv[c];
            }
        }
    }
    __syncthreads();

    // Coalesced flush: 128*69 floats = 2208 uint4
    const uint4* s4 = reinterpret_cast<const uint4*>(u.os);
    uint4* g4 = reinterpret_cast<uint4*>(g_xp + row0 * G_);
    for (int i = tid; i < (RPB * G_) / 4; i += 128)
        g4[i] = s4[i];
}

// =====================================================================
// Kernel 2: GRU scan. ONE WARP PER BATCH, no block barriers.
// Lane j (j<23) owns gate row j; W_hh rows held as 12 k-packed f32x2
// register pairs per gate. h exchanged via per-warp 24-float smem
// buffer read as 12 broadcast LDS.64. x prefetched 2 steps ahead.
// =====================================================================
#define NW 7                       // warps (=batches) per block
#define SCAN_THREADS (NW * 32)

__global__ void __launch_bounds__(SCAN_THREADS, 2) gru_scan_kernel(
    const float* __restrict__ Whh,
    const float* __restrict__ bhh,
    const float* __restrict__ piw,
    const float* __restrict__ pib,
    float* __restrict__ out)
{
    __shared__ __align__(8) float hb[NW][24];

    const int warp = threadIdx.x >> 5;
    const int lane = threadIdx.x & 31;
    const int b    = blockIdx.x * NW + warp;
    const bool act = (lane < H_) && (b < B_);

    // k-packed W_hh rows (pad k=23 -> 0)
    unsigned long long W2r[12], W2z[12], W2n[12];
    float br = 0.f, bz = 0.f, bn = 0.f, pw = 0.f, pb = 0.f;
    if (act) {
        #pragma unroll
        for (int k2 = 0; k2 < 12; k2++) {
            int k = 2 * k2;
            float r0 = Whh[lane * H_ + k];
            float r1 = (k + 1 < H_) ? Whh[lane * H_ + k + 1] : 0.f;
            float z0 = Whh[(H_ + lane) * H_ + k];
            float z1 = (k + 1 < H_) ? Whh[(H_ + lane) * H_ + k + 1] : 0.f;
            float n0 = Whh[(2 * H_ + lane) * H_ + k];
            float n1 = (k + 1 < H_) ? Whh[(2 * H_ + lane) * H_ + k + 1] : 0.f;
            W2r[k2] = pack2_(r0, r1);
            W2z[k2] = pack2_(z0, z1);
            W2n[k2] = pack2_(n0, n1);
        }
        br = bhh[lane]; bz = bhh[H_ + lane]; bn = bhh[2 * H_ + lane];
        pw = piw[lane]; pb = pib[lane];
        hb[warp][lane] = 0.f;
    }
    if (lane == 23) hb[warp][23] = 0.f;   // pad slot
    __syncwarp();

    const int bsafe = act ? b : 0;
    const float* xp = g_xp + (size_t)bsafe * T_ * G_;
    float*       op = out  + (size_t)bsafe * T_ * H_ + lane;

    float h = 0.f;
    // depth-2 prefetch of x gates
    float x0r = 0.f, x0z = 0.f, x0n = 0.f;
    float x1r = 0.f, x1z = 0.f, x1n = 0.f;
    if (act) {
        x0r = xp[lane];      x0z = xp[H_ + lane];      x0n = xp[2 * H_ + lane];
        x1r = xp[G_ + lane]; x1z = xp[G_ + H_ + lane]; x1n = xp[G_ + 2 * H_ + lane];
    }

    for (int t = 0; t < T_; t++) {
        // issue t+2 loads first (covers DRAM latency with 2 full steps)
        float x2r = 0.f, x2z = 0.f, x2n = 0.f;
        if (act && (t + 2 < T_)) {
            const float* q = xp + 2 * G_;
            x2r = q[lane]; x2z = q[H_ + lane]; x2n = q[2 * H_ + lane];
        }

        if (act) {
            unsigned long long ar2 = 0ull, az2 = 0ull, an2 = 0ull;
            const unsigned long long* h2 =
                reinterpret_cast<const unsigned long long*>(hb[warp]);
            #pragma unroll
            for (int k2 = 0; k2 < 12; k2++) {
                unsigned long long hv = h2[k2];      // broadcast LDS.64
                ar2 = fma2_(W2r[k2], hv, ar2);
                az2 = fma2_(W2z[k2], hv, az2);
                an2 = fma2_(W2n[k2], hv, an2);
            }
            float al, ah;
            unpack2_(ar2, al, ah); float ar = br + al + ah;
            unpack2_(az2, al, ah); float az = bz + al + ah;
            unpack2_(an2, al, ah); float an = bn + al + ah;

            float r = sigmoidf_(x0r + ar);
            float z = sigmoidf_(x0z + az);
            float n = tanhf_(fmaf(r, an, x0n));
            h = fmaf(z, h - n, n);               // (1-z)*n + z*h
            *op = fmaf(pw, h, pb);               // action_pred
        }
        __syncwarp();                // all lanes done reading old h
        if (act) hb[warp][lane] = h;
        __syncwarp();                // new h visible before next read

        x0r = x1r; x0z = x1z; x0n = x1n;
        x1r = x2r; x1z = x2z; x1n = x2n;
        xp += G_;
        op += H_;
    }

    if (act)
        out[(size_t)B_ * T_ * H_ + (size_t)b * H_ + lane] = h;  // hidden = hT
}

// =====================================================================
extern "C" void kernel_launch(void* const* d_in, const int* in_sizes, int n_in,
                              void* d_out, int out_size)
{
    const float* ts  = (const float*)d_in[0];  // task_seq (B,T,I)
    const float* Wih = (const float*)d_in[1];  // (69,58)
    const float* Whh = (const float*)d_in[2];  // (69,23)
    const float* bih = (const float*)d_in[3];  // (69,)
    const float* bhh = (const float*)d_in[4];  // (69,)
    const float* piw = (const float*)d_in[5];  // (23,)
    const float* pib = (const float*)d_in[6];  // (23,)
    float* out = (float*)d_out;

    xproj_kernel<<<ROWS_TOTAL / RPB, 128>>>(ts, Wih, bih);
    gru_scan_kernel<<<(B_ + NW - 1) / NW, SCAN_THREADS>>>(Whh, bhh, piw, pib, out);
}